// round 5
// baseline (speedup 1.0000x reference)
#include <cuda_runtime.h>
#include <cuda_bf16.h>
#include <cstdint>

// ============================================================================
// out[64,8] = exp(-1e-4 * ||x_b - c_j||^2) @ fc_w.T + fc_b
//   x: [64, 65536] f32, centers: [500, 65536] f32
// K1: split-K (128 chunks of 512), warp-specialized:
//     - prologue: all 512 threads convert x chunk f32->bf16 (conflict-free STS)
//     - 12 producer warps: stream+convert center 64-row sub-blocks (double buf)
//     - 4 consumer warps: mma.sync bf16 32x32 tiles, fp32 partials to gmem
//     named-barrier ping-pong (FULL/EMPTY per buffer).
// K3: reduce partials over S + finalize norms -> rbf.   K4: fc head.
// Base sm_100 only (harness compiles compute_100: no tcgen05).
// ============================================================================

#define GAMMA_F 1e-4f

static constexpr int S_SPLIT = 128;
static constexpr int KC      = 512;
static constexpr int NB      = 64;
static constexpr int NCPAD   = 512;
static constexpr int SB_ROWS = 64;     // producer sub-block rows
static constexpr int NSB     = 8;      // sub-blocks per chunk (512/64)

// -------- scratch --------
__device__ float g_part [(size_t)NCPAD * S_SPLIT * NB];   // [c][s][b] 16 MB
__device__ float g_csq_p[(size_t)NCPAD * S_SPLIT];
__device__ float g_xsq_p[(size_t)NB    * S_SPLIT];
__device__ float g_rbf  [(size_t)NB * NCPAD];

// -------- helpers --------
__device__ __forceinline__ uint32_t smem_u32(const void* p) {
    uint32_t a;
    asm("{ .reg .u64 t; cvta.to.shared.u64 t, %1; cvt.u32.u64 %0, t; }" : "=r"(a) : "l"(p));
    return a;
}
__device__ __forceinline__ uint32_t sw128(uint32_t off) { return off ^ ((off >> 3) & 0x70); }

// 64-row tile, blocked atoms (8 rows x 64 bf16 = 1024B), 8 atom-rows per k-block
__device__ __forceinline__ uint32_t t64_off(int row, int k) {
    uint32_t b = (((uint32_t)(k >> 6) * 8u + (uint32_t)(row >> 3)) << 10)
               + (uint32_t)(row & 7) * 128u + (uint32_t)(k & 63) * 2u;
    return sw128(b);
}
__device__ __forceinline__ uint32_t pack_bf16x2(float a, float b) {
    __nv_bfloat162 t = __floats2bfloat162_rn(a, b);
    return *reinterpret_cast<uint32_t*>(&t);
}
__device__ __forceinline__ void ldsm_x4(uint32_t* r, uint32_t addr) {
    asm volatile("ldmatrix.sync.aligned.m8n8.x4.shared.b16 {%0,%1,%2,%3}, [%4];"
                 : "=r"(r[0]), "=r"(r[1]), "=r"(r[2]), "=r"(r[3]) : "r"(addr));
}
__device__ __forceinline__ void mma_bf16(float* d, const uint32_t* a, const uint32_t* b) {
    asm volatile("mma.sync.aligned.m16n8k16.row.col.f32.bf16.bf16.f32 "
                 "{%0,%1,%2,%3}, {%4,%5,%6,%7}, {%8,%9}, {%0,%1,%2,%3};"
                 : "+f"(d[0]), "+f"(d[1]), "+f"(d[2]), "+f"(d[3])
                 : "r"(a[0]), "r"(a[1]), "r"(a[2]), "r"(a[3]), "r"(b[0]), "r"(b[1]));
}
#define BAR_SYNC(id, cnt)   asm volatile("bar.sync %0, %1;"   :: "r"(id), "r"(cnt) : "memory")
#define BAR_ARRIVE(id, cnt) asm volatile("bar.arrive %0, %1;" :: "r"(id), "r"(cnt) : "memory")
// barrier ids: FULL[buf]=1+buf, EMPTY[buf]=3+buf, PROD-only=5

// -------- SMEM layout --------
static constexpr int SMEM_X    = 0;                   // 64 x 512 bf16 = 64 KB
static constexpr int SMEM_CB   = 65536;               // 2 bufs x 64 KB
static constexpr int SMEM_SQ   = 65536 + 2 * 65536;   // float sq[2][8][64] = 4 KB
static constexpr int SMEM_TOTAL = SMEM_SQ + 2 * 512 * 4;  // 200704

// ============================================================================
// Kernel 1
// ============================================================================
__global__ void __launch_bounds__(512, 1)
svm_main_kernel(const float* __restrict__ x, const float* __restrict__ centers) {
    extern __shared__ char smem[];
    const uint32_t smem_base = smem_u32(smem);
    float* sq = reinterpret_cast<float*>(smem + SMEM_SQ);
    const int tid = threadIdx.x;
    const int wid = tid >> 5;
    const int lid = tid & 31;
    const int s   = blockIdx.x;
    const size_t k0 = (size_t)s * KC;

    // ---- prologue: convert x chunk (all threads), conflict-free STS ----
    {
        const int row = tid & 63;
        const int kb  = tid >> 6;          // 0..7
        const int r7  = row & 7;
        const float4* xp = reinterpret_cast<const float4*>(x + (size_t)row * 65536 + k0 + kb * 64);
        char* xbase = smem + SMEM_X + ((uint32_t)(kb * 8 + (row >> 3)) << 10) + r7 * 128;
        float a = 0.f;
        #pragma unroll
        for (int j = 0; j < 8; j++) {
            float4 v0 = xp[2 * j], v1 = xp[2 * j + 1];
            a += v0.x * v0.x + v0.y * v0.y + v0.z * v0.z + v0.w * v0.w;
            a += v1.x * v1.x + v1.y * v1.y + v1.z * v1.z + v1.w * v1.w;
            uint4 pk = make_uint4(pack_bf16x2(v0.x, v0.y), pack_bf16x2(v0.z, v0.w),
                                  pack_bf16x2(v1.x, v1.y), pack_bf16x2(v1.z, v1.w));
            *reinterpret_cast<uint4*>(xbase + ((j ^ r7) << 4)) = pk;
        }
        sq[kb * 64 + row] = a;
    }
    __syncthreads();
    if (tid < 64) {
        float t = 0.f;
        #pragma unroll
        for (int kb = 0; kb < 8; kb++) t += sq[kb * 64 + tid];
        g_xsq_p[(size_t)tid * S_SPLIT + s] = t;
    }
    __syncthreads();

    if (wid >= 4) {
        // ================= PRODUCERS (12 warps, 384 threads) =================
        const int p = tid - 128;
        for (int sb = 0; sb < NSB; sb++) {
            const int buf = sb & 1;
            char* cb = smem + SMEM_CB + buf * 65536;
            if (sb >= 2) BAR_SYNC(3 + buf, 512);
            for (int u = p; u < 512; u += 384) {
                const int row = u & 63;
                const int kb  = u >> 6;
                const int r7  = row & 7;
                const int grow = sb * SB_ROWS + row;
                char* cbase = cb + ((uint32_t)(kb * 8 + (row >> 3)) << 10) + r7 * 128;
                float a = 0.f;
                if (grow < 500) {
                    const float4* cp =
                        reinterpret_cast<const float4*>(centers + (size_t)grow * 65536 + k0 + kb * 64);
                    #pragma unroll
                    for (int j = 0; j < 8; j++) {
                        float4 v0 = cp[2 * j], v1 = cp[2 * j + 1];
                        a += v0.x * v0.x + v0.y * v0.y + v0.z * v0.z + v0.w * v0.w;
                        a += v1.x * v1.x + v1.y * v1.y + v1.z * v1.z + v1.w * v1.w;
                        uint4 pk = make_uint4(pack_bf16x2(v0.x, v0.y), pack_bf16x2(v0.z, v0.w),
                                              pack_bf16x2(v1.x, v1.y), pack_bf16x2(v1.z, v1.w));
                        *reinterpret_cast<uint4*>(cbase + ((j ^ r7) << 4)) = pk;
                    }
                } else {
                    #pragma unroll
                    for (int j = 0; j < 8; j++)
                        *reinterpret_cast<uint4*>(cbase + ((j ^ r7) << 4)) = make_uint4(0u, 0u, 0u, 0u);
                }
                sq[buf * 512 + kb * 64 + row] = a;
            }
            BAR_SYNC(5, 384);                       // drains STS; sq ready
            if (p < 64) {
                float t = 0.f;
                #pragma unroll
                for (int kb = 0; kb < 8; kb++) t += sq[buf * 512 + kb * 64 + p];
                g_csq_p[(size_t)(sb * SB_ROWS + p) * S_SPLIT + s] = t;
            }
            BAR_ARRIVE(1 + buf, 512);
        }
    } else {
        // ================= CONSUMERS (4 warps, 32x32 tiles) =================
        const int mr = (wid & 1) * 32;       // center-row base within sub-block
        const int nb = (wid >> 1) * 32;      // batch-col base
        const int sel = lid >> 3;
        const int l7  = lid & 7;
        const int a_row = l7 + (sel & 1) * 8;
        const int a_kd  = (sel >> 1) * 8;
        const int b_row = nb + l7 + (sel >> 1) * 8;
        const int b_kd  = (sel & 1) * 8;
        const uint32_t xb = smem_base + SMEM_X;

        for (int sb = 0; sb < NSB; sb++) {
            const int buf = sb & 1;
            const uint32_t cb = smem_base + SMEM_CB + buf * 65536;
            BAR_SYNC(1 + buf, 512);

            float acc[2][4][4];
            #pragma unroll
            for (int mi = 0; mi < 2; mi++)
                #pragma unroll
                for (int ni = 0; ni < 4; ni++)
                    #pragma unroll
                    for (int i = 0; i < 4; i++) acc[mi][ni][i] = 0.f;

            #pragma unroll 8
            for (int kk = 0; kk < KC; kk += 16) {
                uint32_t af[2][4], bfr[2][4];
                ldsm_x4(af[0], cb + t64_off(mr + a_row,      kk + a_kd));
                ldsm_x4(af[1], cb + t64_off(mr + 16 + a_row, kk + a_kd));
                ldsm_x4(bfr[0], xb + t64_off(b_row,      kk + b_kd));
                ldsm_x4(bfr[1], xb + t64_off(b_row + 16, kk + b_kd));
                #pragma unroll
                for (int mi = 0; mi < 2; mi++)
                    #pragma unroll
                    for (int ni = 0; ni < 4; ni++)
                        mma_bf16(acc[mi][ni], af[mi], &bfr[ni >> 1][(ni & 1) * 2]);
            }

            if (sb < NSB - 2) BAR_ARRIVE(3 + buf, 512);   // free buffer early

            // store partials: rows sb*64 + mr + ..., cols nb + ...
            const int r0 = sb * SB_ROWS + mr + (lid >> 2);
            const int c0 = nb + (lid & 3) * 2;
            #pragma unroll
            for (int mi = 0; mi < 2; mi++) {
                #pragma unroll
                for (int ni = 0; ni < 4; ni++) {
                    const int col = c0 + 8 * ni;
                    float* b0 = g_part + (((size_t)(r0 + 16 * mi)     * S_SPLIT + s) << 6) + col;
                    float* b1 = g_part + (((size_t)(r0 + 16 * mi + 8) * S_SPLIT + s) << 6) + col;
                    *reinterpret_cast<float2*>(b0) = make_float2(acc[mi][ni][0], acc[mi][ni][1]);
                    *reinterpret_cast<float2*>(b1) = make_float2(acc[mi][ni][2], acc[mi][ni][3]);
                }
            }
        }
    }
}

// ============================================================================
// Kernel 3: reduce partials over S + finalize norms -> rbf[b][c]
// ============================================================================
__global__ void svm_rbf_kernel() {
    __shared__ float red [4][NB];
    __shared__ float redx[4][NB];
    __shared__ float s_csq;
    const int c   = blockIdx.x;          // 0..499
    const int tid = threadIdx.x;         // 256
    const int sp  = tid >> 6;
    const int b   = tid & 63;

    // xsq partials: 4 threads per batch row
    {
        const int br = tid >> 2, q = tid & 3;
        const float* xp = g_xsq_p + (size_t)br * S_SPLIT + q * 32;
        float v = 0.f;
        #pragma unroll
        for (int i = 0; i < 32; i++) v += xp[i];
        redx[q][br] = v;
    }
    // csq: warp 0
    if (tid < 32) {
        const float* cp = g_csq_p + (size_t)c * S_SPLIT + tid * 4;
        float v = cp[0] + cp[1] + cp[2] + cp[3];
        #pragma unroll
        for (int d = 16; d > 0; d >>= 1) v += __shfl_xor_sync(0xffffffffu, v, d);
        if (tid == 0) s_csq = v;
    }
    // cross partials
    {
        const float* p = g_part + ((size_t)c * S_SPLIT + (size_t)sp * 32) * NB + b;
        float a = 0.f;
        #pragma unroll
        for (int i = 0; i < 32; i++) a += p[(size_t)i * NB];
        red[sp][b] = a;
    }
    __syncthreads();
    if (tid < NB) {
        float cross = red[0][tid] + red[1][tid] + red[2][tid] + red[3][tid];
        float xs    = redx[0][tid] + redx[1][tid] + redx[2][tid] + redx[3][tid];
        float dist  = xs - 2.0f * cross + s_csq;
        g_rbf[(size_t)tid * NCPAD + c] = expf(-GAMMA_F * dist);
    }
}

// ============================================================================
// Kernel 4: out[b][i] = sum_c rbf[b][c] * fc_w[i][c] + fc_b[i]
// ============================================================================
__global__ void svm_fc_kernel(const float* __restrict__ fc_w,
                              const float* __restrict__ fc_b,
                              float* __restrict__ out) {
    const int b   = blockIdx.x;
    const int w   = threadIdx.x >> 5;
    const int lid = threadIdx.x & 31;
    const float* rr = g_rbf + (size_t)b * NCPAD;
    float acc = 0.f;
    for (int c = lid; c < 500; c += 32)
        acc += rr[c] * fc_w[w * 500 + c];
    #pragma unroll
    for (int d = 16; d > 0; d >>= 1) acc += __shfl_xor_sync(0xffffffffu, acc, d);
    if (lid == 0) out[b * 8 + w] = acc + fc_b[w];
}

// ============================================================================
extern "C" void kernel_launch(void* const* d_in, const int* in_sizes, int n_in,
                              void* d_out, int out_size) {
    const float* x       = (const float*)d_in[0];
    const float* centers = (const float*)d_in[1];
    const float* fc_w    = (const float*)d_in[2];
    const float* fc_b    = (const float*)d_in[3];
    float* out = (float*)d_out;

    cudaFuncSetAttribute(svm_main_kernel, cudaFuncAttributeMaxDynamicSharedMemorySize, SMEM_TOTAL);

    svm_main_kernel<<<S_SPLIT, 512, SMEM_TOTAL>>>(x, centers);
    svm_rbf_kernel<<<500, 256>>>();
    svm_fc_kernel<<<NB, 256>>>(fc_w, fc_b, out);
}

// round 6
// speedup vs baseline: 1.2545x; 1.2545x over previous
#include <cuda_runtime.h>
#include <cuda_bf16.h>
#include <cuda_fp16.h>
#include <cstdint>

// ============================================================================
// out[64,8] = exp(-1e-4 * ||x_b - c_j||^2) @ fc_w.T + fc_b
//   x: [64, 65536] f32, centers: [500, 65536] f32
// K1: split-K, KC=256, grid=256, 256 thr/CTA, 2-3 CTAs/SM (occupancy overlap,
//     no warp specialization). Per CTA: convert x chunk (32KB bf16 tile), then
//     8 sub-blocks of 64 center rows: convert -> mma.sync bf16 -> f16 partials.
//     Exact fp32 norms fused into conversion.
// K2: rbf reduce (f16 partials, coalesced half2). K3: fc head (8 blocks).
// Base sm_100 only (harness compiles compute_100: no tcgen05).
// ============================================================================

#define GAMMA_F 1e-4f

static constexpr int S_SPLIT = 256;   // K chunks
static constexpr int KC      = 256;   // K per chunk
static constexpr int NB      = 64;    // batch
static constexpr int NCPAD   = 512;
static constexpr int NSB     = 8;     // 64-row center sub-blocks per chunk

// -------- scratch --------
__device__ __half g_parth[(size_t)NCPAD * S_SPLIT * NB];  // [c][s][b] 16 MB f16
__device__ float  g_csq_p[(size_t)NCPAD * S_SPLIT];
__device__ float  g_xsq_p[(size_t)NB    * S_SPLIT];       // [b][s]
__device__ float  g_rbf  [(size_t)NCPAD * NB];            // [c][b]

// -------- helpers --------
__device__ __forceinline__ uint32_t smem_u32(const void* p) {
    uint32_t a;
    asm("{ .reg .u64 t; cvta.to.shared.u64 t, %1; cvt.u32.u64 %0, t; }" : "=r"(a) : "l"(p));
    return a;
}
__device__ __forceinline__ uint32_t sw128(uint32_t off) { return off ^ ((off >> 3) & 0x70); }

// 64-row x 256-k bf16 tile, blocked atoms (8 rows x 64 bf16 = 1024B)
__device__ __forceinline__ uint32_t t64_off(int row, int k) {
    uint32_t b = (((uint32_t)(k >> 6) * 8u + (uint32_t)(row >> 3)) << 10)
               + (uint32_t)(row & 7) * 128u + (uint32_t)(k & 63) * 2u;
    return sw128(b);
}
__device__ __forceinline__ uint32_t pack_bf16x2(float a, float b) {
    __nv_bfloat162 t = __floats2bfloat162_rn(a, b);
    return *reinterpret_cast<uint32_t*>(&t);
}
__device__ __forceinline__ void ldsm_x4(uint32_t* r, uint32_t addr) {
    asm volatile("ldmatrix.sync.aligned.m8n8.x4.shared.b16 {%0,%1,%2,%3}, [%4];"
                 : "=r"(r[0]), "=r"(r[1]), "=r"(r[2]), "=r"(r[3]) : "r"(addr));
}
__device__ __forceinline__ void mma_bf16(float* d, const uint32_t* a, const uint32_t* b) {
    asm volatile("mma.sync.aligned.m16n8k16.row.col.f32.bf16.bf16.f32 "
                 "{%0,%1,%2,%3}, {%4,%5,%6,%7}, {%8,%9}, {%0,%1,%2,%3};"
                 : "+f"(d[0]), "+f"(d[1]), "+f"(d[2]), "+f"(d[3])
                 : "r"(a[0]), "r"(a[1]), "r"(a[2]), "r"(a[3]), "r"(b[0]), "r"(b[1]));
}

// -------- SMEM layout (dynamic): x 32KB | c 32KB | sq 1KB --------
static constexpr int SMEM_X     = 0;
static constexpr int SMEM_C     = 32768;
static constexpr int SMEM_SQ    = 65536;
static constexpr int SMEM_TOTAL = 65536 + 4 * 64 * 4;   // 66560

// ============================================================================
// Kernel 1
// ============================================================================
__global__ void __launch_bounds__(256, 3)
svm_main_kernel(const float* __restrict__ x, const float* __restrict__ centers) {
    extern __shared__ char smem[];
    const uint32_t smem_base = smem_u32(smem);
    float* sq = reinterpret_cast<float*>(smem + SMEM_SQ);
    const int tid = threadIdx.x;
    const int wid = tid >> 5;
    const int lid = tid & 31;
    const int s   = blockIdx.x;
    const size_t k0 = (size_t)s * KC;

    const int row = tid & 63;          // convert-role row
    const int kb  = tid >> 6;          // 0..3 (64-k block)
    const int r7  = row & 7;
    const uint32_t conv_off = ((uint32_t)(kb * 8 + (row >> 3)) << 10) + (uint32_t)r7 * 128u;

    // ---- prologue: convert x chunk (all threads), conflict-free STS ----
    {
        const float4* xp = reinterpret_cast<const float4*>(x + (size_t)row * 65536 + k0 + kb * 64);
        char* xbase = smem + SMEM_X + conv_off;
        float a = 0.f;
        #pragma unroll
        for (int j = 0; j < 8; j++) {
            float4 v0 = xp[2 * j], v1 = xp[2 * j + 1];
            a += v0.x * v0.x + v0.y * v0.y + v0.z * v0.z + v0.w * v0.w;
            a += v1.x * v1.x + v1.y * v1.y + v1.z * v1.z + v1.w * v1.w;
            uint4 pk = make_uint4(pack_bf16x2(v0.x, v0.y), pack_bf16x2(v0.z, v0.w),
                                  pack_bf16x2(v1.x, v1.y), pack_bf16x2(v1.z, v1.w));
            *reinterpret_cast<uint4*>(xbase + ((j ^ r7) << 4)) = pk;
        }
        sq[kb * 64 + row] = a;
    }
    __syncthreads();
    if (tid < 64) {
        g_xsq_p[(size_t)tid * S_SPLIT + s] =
            sq[tid] + sq[64 + tid] + sq[128 + tid] + sq[192 + tid];
    }

    // ---- MMA lane constants: 8 warps = 2(M:32) x 4(N:16) ----
    const int mr    = (wid & 1) * 32;
    const int nbase = (wid >> 1) * 16;
    const int sel = lid >> 3;
    const int l7  = lid & 7;
    const int a_row = l7 + (sel & 1) * 8;
    const int a_kd  = (sel >> 1) * 8;
    const int b_row = nbase + l7 + (sel >> 1) * 8;
    const int b_kd  = (sel & 1) * 8;
    const uint32_t xb = smem_base + SMEM_X;
    const uint32_t cb = smem_base + SMEM_C;

    for (int sb = 0; sb < NSB; sb++) {
        __syncthreads();   // WAR: prev MMA done (also covers prologue xsq read)

        // ---- convert center sub-block (64 rows) ----
        {
            const int grow = sb * 64 + row;
            char* cbase = smem + SMEM_C + conv_off;
            float a = 0.f;
            if (grow < 500) {
                const float4* cp =
                    reinterpret_cast<const float4*>(centers + (size_t)grow * 65536 + k0 + kb * 64);
                #pragma unroll
                for (int j = 0; j < 8; j++) {
                    float4 v0 = cp[2 * j], v1 = cp[2 * j + 1];
                    a += v0.x * v0.x + v0.y * v0.y + v0.z * v0.z + v0.w * v0.w;
                    a += v1.x * v1.x + v1.y * v1.y + v1.z * v1.z + v1.w * v1.w;
                    uint4 pk = make_uint4(pack_bf16x2(v0.x, v0.y), pack_bf16x2(v0.z, v0.w),
                                          pack_bf16x2(v1.x, v1.y), pack_bf16x2(v1.z, v1.w));
                    *reinterpret_cast<uint4*>(cbase + ((j ^ r7) << 4)) = pk;
                }
            } else {
                #pragma unroll
                for (int j = 0; j < 8; j++)
                    *reinterpret_cast<uint4*>(cbase + ((j ^ r7) << 4)) = make_uint4(0u, 0u, 0u, 0u);
            }
            sq[kb * 64 + row] = a;
        }
        __syncthreads();

        if (tid < 64) {
            g_csq_p[(size_t)(sb * 64 + tid) * S_SPLIT + s] =
                sq[tid] + sq[64 + tid] + sq[128 + tid] + sq[192 + tid];
        }

        // ---- MMA: 32x16 warp tile over KC=256 ----
        float acc[2][2][4];
        #pragma unroll
        for (int mi = 0; mi < 2; mi++)
            #pragma unroll
            for (int g = 0; g < 2; g++)
                #pragma unroll
                for (int i = 0; i < 4; i++) acc[mi][g][i] = 0.f;

        #pragma unroll 8
        for (int kk = 0; kk < KC; kk += 16) {
            uint32_t af0[4], af1[4], bf[4];
            ldsm_x4(af0, cb + t64_off(mr + a_row,      kk + a_kd));
            ldsm_x4(af1, cb + t64_off(mr + 16 + a_row, kk + a_kd));
            ldsm_x4(bf,  xb + t64_off(b_row,           kk + b_kd));
            mma_bf16(acc[0][0], af0, bf);
            mma_bf16(acc[0][1], af0, bf + 2);
            mma_bf16(acc[1][0], af1, bf);
            mma_bf16(acc[1][1], af1, bf + 2);
        }

        // ---- store f16 partials ----
        {
            const int r0 = sb * 64 + mr + (lid >> 2);
            const int c0 = nbase + (lid & 3) * 2;
            #pragma unroll
            for (int mi = 0; mi < 2; mi++) {
                #pragma unroll
                for (int g = 0; g < 2; g++) {
                    const int col = c0 + 8 * g;
                    __half* b0 = g_parth + (((size_t)(r0 + 16 * mi)     * S_SPLIT + s) << 6) + col;
                    __half* b1 = g_parth + (((size_t)(r0 + 16 * mi + 8) * S_SPLIT + s) << 6) + col;
                    *reinterpret_cast<__half2*>(b0) = __floats2half2_rn(acc[mi][g][0], acc[mi][g][1]);
                    *reinterpret_cast<__half2*>(b1) = __floats2half2_rn(acc[mi][g][2], acc[mi][g][3]);
                }
            }
        }
    }
}

// ============================================================================
// Kernel 2: reduce partials over S + finalize norms -> rbf[c][b]
// ============================================================================
__global__ void svm_rbf_kernel() {
    __shared__ float red [8][NB];
    __shared__ float redx[4][NB];
    __shared__ float s_csq;
    const int c   = blockIdx.x;          // 0..499
    const int tid = threadIdx.x;         // 256
    const int sp   = tid >> 5;           // 0..7 (32 s-values each)
    const int lane = tid & 31;           // b-pair index

    // cross partials: coalesced half2 stream
    {
        const __half2* p =
            reinterpret_cast<const __half2*>(g_parth + ((size_t)c * S_SPLIT + sp * 32) * NB) + lane;
        float2 a = make_float2(0.f, 0.f);
        #pragma unroll
        for (int i = 0; i < 32; i++) {
            float2 f = __half22float2(p[(size_t)i * 32]);
            a.x += f.x; a.y += f.y;
        }
        red[sp][2 * lane]     = a.x;
        red[sp][2 * lane + 1] = a.y;
    }
    // xsq: 4 threads per batch row, contiguous 64-s segments
    {
        const int b = tid >> 2, q = tid & 3;
        const float4* xp = reinterpret_cast<const float4*>(g_xsq_p + (size_t)b * S_SPLIT + q * 64);
        float v = 0.f;
        #pragma unroll
        for (int i = 0; i < 16; i++) {
            float4 t = xp[i];
            v += t.x + t.y + t.z + t.w;
        }
        redx[q][b] = v;
    }
    // csq: warp 0
    if (tid < 32) {
        const float4* cp = reinterpret_cast<const float4*>(g_csq_p + (size_t)c * S_SPLIT);
        float4 t0 = cp[tid], t1 = cp[tid + 32];
        float v = t0.x + t0.y + t0.z + t0.w + t1.x + t1.y + t1.z + t1.w;
        #pragma unroll
        for (int d = 16; d > 0; d >>= 1) v += __shfl_xor_sync(0xffffffffu, v, d);
        if (tid == 0) s_csq = v;
    }
    __syncthreads();
    if (tid < NB) {
        float cross = 0.f, xs = 0.f;
        #pragma unroll
        for (int i = 0; i < 8; i++) cross += red[i][tid];
        #pragma unroll
        for (int i = 0; i < 4; i++) xs += redx[i][tid];
        float dist = xs - 2.0f * cross + s_csq;
        g_rbf[(size_t)c * NB + tid] = expf(-GAMMA_F * dist);
    }
}

// ============================================================================
// Kernel 3: out[b][i] = sum_c rbf[c][b] * fc_w[i][c] + fc_b[i]
// ============================================================================
__global__ void svm_fc_kernel(const float* __restrict__ fc_w,
                              const float* __restrict__ fc_b,
                              float* __restrict__ out) {
    __shared__ float sred[8][NB];
    const int i = blockIdx.x;            // 0..7 output feature
    const int t = threadIdx.x;           // 512
    const int b = t & 63;
    const int g = t >> 6;                // 0..7 c-group
    float acc = 0.f;
    for (int c = g; c < 500; c += 8)
        acc += g_rbf[(size_t)c * NB + b] * fc_w[i * 500 + c];
    sred[g][b] = acc;
    __syncthreads();
    if (t < NB) {
        float v = 0.f;
        #pragma unroll
        for (int k = 0; k < 8; k++) v += sred[k][t];
        out[t * 8 + i] = v + fc_b[i];
    }
}

// ============================================================================
extern "C" void kernel_launch(void* const* d_in, const int* in_sizes, int n_in,
                              void* d_out, int out_size) {
    const float* x       = (const float*)d_in[0];
    const float* centers = (const float*)d_in[1];
    const float* fc_w    = (const float*)d_in[2];
    const float* fc_b    = (const float*)d_in[3];
    float* out = (float*)d_out;

    cudaFuncSetAttribute(svm_main_kernel, cudaFuncAttributeMaxDynamicSharedMemorySize, SMEM_TOTAL);

    svm_main_kernel<<<S_SPLIT, 256, SMEM_TOTAL>>>(x, centers);
    svm_rbf_kernel<<<500, 256>>>();
    svm_fc_kernel<<<8, 512>>>(fc_w, fc_b, out);
}